// round 1
// baseline (speedup 1.0000x reference)
#include <cuda_runtime.h>
#include <cuda_bf16.h>
#include <math.h>

#define NUM_ENT 14541
#define EMBED_DIM 200
#define BATCH 256
#define GAMMA 9.0f

// Scratch for obj = ent[sub] + rel[rel]  (256 x 200 fp32 = 200 KB)
__device__ float g_obj[BATCH * EMBED_DIM];

__global__ void obj_kernel(const float* __restrict__ ent,
                           const float* __restrict__ relE,
                           const int* __restrict__ sub,
                           const int* __restrict__ rel) {
    int b = blockIdx.x;
    int s = sub[b];
    int r = rel[b];
    for (int d = threadIdx.x; d < EMBED_DIM; d += blockDim.x) {
        g_obj[b * EMBED_DIM + d] = ent[s * EMBED_DIM + d] + relE[r * EMBED_DIM + d];
    }
}

// 64(b) x 64(n) block tile, 256 threads, 4x4 register micro-tile, K-step = 8.
// smem layout [k][row] (transposed) with pad 68 -> conflict-free STS, aligned LDS.128.
__global__ __launch_bounds__(256, 4)
void score_kernel(const float* __restrict__ ent, float* __restrict__ out) {
    __shared__ float obj_s[8][68];
    __shared__ float ent_s[8][68];

    const int n0 = blockIdx.x * 64;
    const int b0 = blockIdx.y * 64;
    const int t  = threadIdx.x;
    const int tx = t & 15;   // n-group
    const int ty = t >> 4;   // b-group

    // loader role: threads 0..127 load obj tile, 128..255 load ent tile
    const int  lt    = t & 127;
    const int  lrow  = lt >> 1;      // 0..63
    const int  lpart = lt & 1;       // which half of the 8-dim chunk
    const bool isEnt = (t >= 128);

    float acc[4][4];
#pragma unroll
    for (int i = 0; i < 4; i++)
#pragma unroll
        for (int j = 0; j < 4; j++) acc[i][j] = 0.0f;

    const int nrow = n0 + lrow;

    for (int kk = 0; kk < EMBED_DIM; kk += 8) {
        // issue the global load early (hides L2 latency behind the sync)
        float4 v;
        if (!isEnt) {
            v = *(const float4*)&g_obj[(b0 + lrow) * EMBED_DIM + kk + lpart * 4];
        } else if (nrow < NUM_ENT) {
            v = *(const float4*)&ent[(size_t)nrow * EMBED_DIM + kk + lpart * 4];
        } else {
            v = make_float4(0.f, 0.f, 0.f, 0.f);
        }

        __syncthreads();  // previous iteration's reads complete before overwrite

        float* dst = isEnt ? &ent_s[0][0] : &obj_s[0][0];
        const int kb = lpart * 4;
        dst[(kb + 0) * 68 + lrow] = v.x;
        dst[(kb + 1) * 68 + lrow] = v.y;
        dst[(kb + 2) * 68 + lrow] = v.z;
        dst[(kb + 3) * 68 + lrow] = v.w;

        __syncthreads();

#pragma unroll
        for (int k = 0; k < 8; k++) {
            float4 a4 = *(const float4*)&obj_s[k][ty * 4];
            float4 b4 = *(const float4*)&ent_s[k][tx * 4];
            float av[4] = {a4.x, a4.y, a4.z, a4.w};
            float bv[4] = {b4.x, b4.y, b4.z, b4.w};
#pragma unroll
            for (int i = 0; i < 4; i++)
#pragma unroll
                for (int j = 0; j < 4; j++)
                    acc[i][j] += fabsf(av[i] - bv[j]);
        }
    }

    // epilogue: score = sigmoid(GAMMA - dist) = 1 / (1 + exp(dist - GAMMA))
#pragma unroll
    for (int i = 0; i < 4; i++) {
        const int b = b0 + ty * 4 + i;
#pragma unroll
        for (int j = 0; j < 4; j++) {
            const int n = n0 + tx * 4 + j;
            if (n < NUM_ENT) {
                float s = 1.0f / (1.0f + __expf(acc[i][j] - GAMMA));
                out[(size_t)b * NUM_ENT + n] = s;
            }
        }
    }
}

extern "C" void kernel_launch(void* const* d_in, const int* in_sizes, int n_in,
                              void* d_out, int out_size) {
    const float* ent  = (const float*)d_in[0];   // [14541, 200]
    const float* relE = (const float*)d_in[1];   // [474, 200]
    const int*   sub  = (const int*)d_in[2];     // [256]
    const int*   rel  = (const int*)d_in[3];     // [256]
    // d_in[4] = neg_ents: unused by the reference
    float* out = (float*)d_out;                  // [256, 14541]

    obj_kernel<<<BATCH, 128>>>(ent, relE, sub, rel);

    dim3 grid((NUM_ENT + 63) / 64, BATCH / 64);  // 228 x 4
    score_kernel<<<grid, 256>>>(ent, out);
}

// round 2
// speedup vs baseline: 1.0320x; 1.0320x over previous
#include <cuda_runtime.h>
#include <cuda_bf16.h>
#include <math.h>

#define NUM_ENT 14541
#define EMBED_DIM 200
#define BATCH 256
#define GAMMA 9.0f

// Scratch for obj = ent[sub] + rel[rel]  (256 x 200 fp32 = 200 KB)
__device__ float g_obj[BATCH * EMBED_DIM];

__global__ void obj_kernel(const float* __restrict__ ent,
                           const float* __restrict__ relE,
                           const int* __restrict__ sub,
                           const int* __restrict__ rel) {
    int b = blockIdx.x;
    int s = sub[b];
    int r = rel[b];
    for (int d = threadIdx.x; d < EMBED_DIM; d += blockDim.x) {
        g_obj[b * EMBED_DIM + d] = ent[s * EMBED_DIM + d] + relE[r * EMBED_DIM + d];
    }
}

// Tile: 64(b) x 128(n) per block, 128 threads, 8x8 register micro-tile.
// smem transposed [k][row], double-buffered, one barrier per 8-dim K-step.
// Fragment n-indices are {ng*4+j, 64+ng*4+j} -> conflict-free LDS.128.
__global__ __launch_bounds__(128, 4)
void score_kernel(const float* __restrict__ ent, float* __restrict__ out) {
    __shared__ __align__(16) float obj_s[2][8][68];    // [buf][k][b-col]
    __shared__ __align__(16) float ent_s[2][8][132];   // [buf][k][n-col]

    const int n0 = blockIdx.x * 128;
    const int b0 = blockIdx.y * 64;
    const int t  = threadIdx.x;
    const int ng = t & 15;    // n-group (0..15)
    const int bg = t >> 4;    // b-group (0..7)

    // loader roles
    const int orow  = t >> 1;                 // obj row 0..63
    const int opart = t & 1;                  // which float4 of the 8-dim chunk
    const size_t erow = (size_t)min(n0 + t, NUM_ENT - 1);  // ent row (clamped)

    float acc[8][8];
#pragma unroll
    for (int i = 0; i < 8; i++)
#pragma unroll
        for (int j = 0; j < 8; j++) acc[i][j] = 0.0f;

    const float* obj_src = &g_obj[(b0 + orow) * EMBED_DIM + opart * 4];
    const float* ent_src = &ent[erow * EMBED_DIM];

    // ---- prefetch + store tile 0 ----
    {
        float4 ov  = *(const float4*)(obj_src + 0);
        float4 ev0 = *(const float4*)(ent_src + 0);
        float4 ev1 = *(const float4*)(ent_src + 4);
        const int kb = opart * 4;
        obj_s[0][kb + 0][orow] = ov.x;
        obj_s[0][kb + 1][orow] = ov.y;
        obj_s[0][kb + 2][orow] = ov.z;
        obj_s[0][kb + 3][orow] = ov.w;
        ent_s[0][0][t] = ev0.x; ent_s[0][1][t] = ev0.y;
        ent_s[0][2][t] = ev0.z; ent_s[0][3][t] = ev0.w;
        ent_s[0][4][t] = ev1.x; ent_s[0][5][t] = ev1.y;
        ent_s[0][6][t] = ev1.z; ent_s[0][7][t] = ev1.w;
    }
    __syncthreads();

    const int NITER = EMBED_DIM / 8;  // 25
    for (int it = 0; it < NITER; ++it) {
        const int cur = it & 1;

        // prefetch next K-chunk (global -> regs), overlapped with compute
        float4 pov, pev0, pev1;
        const bool have_next = (it + 1 < NITER);
        if (have_next) {
            const int kk = (it + 1) * 8;
            pov  = *(const float4*)(obj_src + kk);
            pev0 = *(const float4*)(ent_src + kk);
            pev1 = *(const float4*)(ent_src + kk + 4);
        }

#pragma unroll
        for (int k = 0; k < 8; ++k) {
            float4 a0 = *(const float4*)&obj_s[cur][k][bg * 4];
            float4 a1 = *(const float4*)&obj_s[cur][k][32 + bg * 4];
            float4 c0 = *(const float4*)&ent_s[cur][k][ng * 4];
            float4 c1 = *(const float4*)&ent_s[cur][k][64 + ng * 4];
            float av[8] = {a0.x, a0.y, a0.z, a0.w, a1.x, a1.y, a1.z, a1.w};
            float bv[8] = {c0.x, c0.y, c0.z, c0.w, c1.x, c1.y, c1.z, c1.w};
#pragma unroll
            for (int i = 0; i < 8; i++)
#pragma unroll
                for (int j = 0; j < 8; j++)
                    acc[i][j] += fabsf(av[i] - bv[j]);
        }

        if (have_next) {
            const int nxt = cur ^ 1;
            const int kb = opart * 4;
            obj_s[nxt][kb + 0][orow] = pov.x;
            obj_s[nxt][kb + 1][orow] = pov.y;
            obj_s[nxt][kb + 2][orow] = pov.z;
            obj_s[nxt][kb + 3][orow] = pov.w;
            ent_s[nxt][0][t] = pev0.x; ent_s[nxt][1][t] = pev0.y;
            ent_s[nxt][2][t] = pev0.z; ent_s[nxt][3][t] = pev0.w;
            ent_s[nxt][4][t] = pev1.x; ent_s[nxt][5][t] = pev1.y;
            ent_s[nxt][6][t] = pev1.z; ent_s[nxt][7][t] = pev1.w;
        }
        __syncthreads();
    }

    // epilogue: score = 1 / (1 + exp(dist - GAMMA))
#pragma unroll
    for (int i = 0; i < 8; ++i) {
        const int b = b0 + bg * 4 + (i & 3) + 32 * (i >> 2);
        const size_t rowoff = (size_t)b * NUM_ENT;
#pragma unroll
        for (int j = 0; j < 8; ++j) {
            const int n = n0 + ng * 4 + (j & 3) + 64 * (j >> 2);
            if (n < NUM_ENT) {
                out[rowoff + n] = 1.0f / (1.0f + __expf(acc[i][j] - GAMMA));
            }
        }
    }
}

extern "C" void kernel_launch(void* const* d_in, const int* in_sizes, int n_in,
                              void* d_out, int out_size) {
    const float* ent  = (const float*)d_in[0];   // [14541, 200]
    const float* relE = (const float*)d_in[1];   // [474, 200]
    const int*   sub  = (const int*)d_in[2];     // [256]
    const int*   rel  = (const int*)d_in[3];     // [256]
    // d_in[4] = neg_ents: unused by the reference
    float* out = (float*)d_out;                  // [256, 14541]

    obj_kernel<<<BATCH, 128>>>(ent, relE, sub, rel);

    dim3 grid((NUM_ENT + 127) / 128, BATCH / 64);  // 114 x 4 = 456 blocks
    score_kernel<<<grid, 128>>>(ent, out);
}